// round 15
// baseline (speedup 1.0000x reference)
#include <cuda_runtime.h>
#include <math.h>

#define NQ 12
#define DIM 4096
#define NL 4
#define NC 10
#define BATCH 512
#define TPB 512
#define NBLK (BATCH / 2)     // 256 blocks, 2 samples per block (f32x2 lanes)
#define BN_EPS 1e-5f
#define NSWEEP (NL * 4)      // 16 three-qubit sweeps

typedef unsigned long long u64;

// Scratch for softmax probs (B x NC) + completion counter. Allocation-free.
__device__ float g_probs[BATCH * NC];
__device__ unsigned g_cnt = 0;

// ---------------- compile-time GF(2) circuit tables ----------------
// storage swizzle: amplitude i lives at slot i ^ (i>>4) (bijective, XOR-linear)
constexpr int csw(int i) { return i ^ (i >> 4); }
constexpr int cctz(int v) { int n = 0; while (!(v & 1)) { v >>= 1; n++; } return n; }
constexpr int cmsb(int v) { int n = -1; while (v) { v >>= 1; n++; } return n; }

// echelon insert (indexed by MSB). true iff v independent of current set.
constexpr bool ins_ech(int* ech, int v) {
    while (v) {
        const int m = cmsb(v);
        if (!ech[m]) { ech[m] = v; return true; }
        v ^= ech[m];
    }
    return false;
}
// reduce v by echelon; 0 iff v in span
constexpr int red_ech(const int* ech, int v) {
    while (v) {
        const int m = cmsb(v);
        if (!ech[m]) return v;
        v ^= ech[m];
    }
    return 0;
}

struct Tab {
    int sp[NSWEEP][12];   // per sweep: sw(v1), sw(v2), sw(v3), sw(bas[0..8])
    int dz[NC];           // swizzled parity masks for <Z_c> with C^4 folded in
};

constexpr Tab make_tab() {
    Tab t{};
    int M[NQ] = {}, Mi[NQ] = {};
    for (int r = 0; r < NQ; r++) { M[r] = 1 << r; Mi[r] = 1 << r; }
    for (int q = 0; q < NQ; q++) {             // CNOT(q, q+1), q ascending
        int pc = NQ - 1 - q, pt = NQ - 1 - ((q + 1) % NQ);
        M[pt] ^= M[pc];
    }
    for (int q = NQ - 1; q >= 0; q--) {        // inverse: reversed order
        int pc = NQ - 1 - q, pt = NQ - 1 - ((q + 1) % NQ);
        Mi[pt] ^= Mi[pc];
    }
    int Mp[NL + 1][NQ] = {}, Mip[NL][NQ] = {};
    int P[NQ] = {}, Pi_[NQ] = {};
    for (int r = 0; r < NQ; r++) { P[r] = 1 << r; Pi_[r] = 1 << r; }
    for (int l = 0; l <= NL; l++) {
        for (int r = 0; r < NQ; r++) Mp[l][r] = P[r];
        if (l < NL) for (int r = 0; r < NQ; r++) Mip[l][r] = Pi_[r];
        int Pn[NQ] = {}, Pin[NQ] = {};
        for (int r = 0; r < NQ; r++) {
            int acc = 0, acci = 0;
            for (int s = 0; s < NQ; s++) {
                if ((M[r]  >> s) & 1) acc  ^= P[s];
                if ((Mi[r] >> s) & 1) acci ^= Pi_[s];
            }
            Pn[r] = acc; Pin[r] = acci;
        }
        for (int r = 0; r < NQ; r++) { P[r] = Pn[r]; Pi_[r] = Pin[r]; }
    }
    // raw gate masks per sweep (columns of M^{-l})
    int rawv[NSWEEP][3] = {};
    for (int idx = 0; idx < NSWEEP; idx++) {
        const int l = idx / 4, g = idx % 4;
        for (int j = 0; j < 3; j++) {
            const int pb = NQ - 1 - (3 * g + j);
            for (int r = 0; r < NQ; r++)
                rawv[idx][j] |= ((Mip[l][r] >> pb) & 1) << r;
        }
    }
    for (int idx = 0; idx < NSWEEP; idx++) {
        const int l = idx / 4, g = idx % 4;
        int D[3] = {};
        for (int j = 0; j < 3; j++) D[j] = Mp[l][NQ - 1 - (3 * g + j)];
        // RREF of the 3 duals
        int pv[3] = {};
        for (int j = 0; j < 3; j++) {
            pv[j] = cctz(D[j]);
            for (int i = 0; i < 3; i++)
                if (i != j && ((D[i] >> pv[j]) & 1)) D[i] ^= D[j];
        }
        // null-space basis (9 vectors)
        int bas[9] = {}; int nb = 0;
        const int pmask = (1 << pv[0]) | (1 << pv[1]) | (1 << pv[2]);
        for (int j = 0; j < NQ; j++) {
            if ((pmask >> j) & 1) continue;
            bas[nb++] = (1 << j) ^ (((D[0] >> j) & 1) << pv[0])
                                 ^ (((D[1] >> j) & 1) << pv[1])
                                 ^ (((D[2] >> j) & 1) << pv[2]);
        }
        int sel[9] = {}; int nsel = 0;
        int ech12[12] = {};           // echelon of chosen vectors
        if (idx >= 1 && idx < 3) {
            // sparsity sweeps: support-subspace vectors on low tid bits so the
            // active set == {tid < 8^swp}; bank order is irrelevant here
            // (only 8/64 threads touch SMEM).
            int Wech[12] = {};        // span of masks of sweeps 0..idx
            for (int s2 = 0; s2 <= idx; s2++)
                for (int j = 0; j < 3; j++) ins_ech(Wech, rawv[s2][j]);
            for (int c = 1; c < 512 && nsel < 3 * idx; c++) {
                int vv = 0;
                for (int bb = 0; bb < 9; bb++) if ((c >> bb) & 1) vv ^= bas[bb];
                if (red_ech(Wech, vv)) continue;              // not in support
                int t12[12] = {};
                for (int ii = 0; ii < 12; ii++) t12[ii] = ech12[ii];
                if (!ins_ech(t12, vv)) continue;              // dependent
                for (int ii = 0; ii < 12; ii++) ech12[ii] = t12[ii];
                sel[nsel++] = vv;
            }
            int echn[4] = {};
            for (int s0 = 0; s0 < nsel; s0++) ins_ech(echn, csw(sel[s0]) & 15);
            int bankgoal = nsel + 4; if (bankgoal > 9) bankgoal = 9;
            for (int c = 1; c < 512 && nsel < bankgoal; c++) {
                int vv = 0;
                for (int bb = 0; bb < 9; bb++) if ((c >> bb) & 1) vv ^= bas[bb];
                int tn[4] = {echn[0], echn[1], echn[2], echn[3]};
                if (!ins_ech(tn, csw(vv) & 15)) continue;
                int t12[12] = {};
                for (int ii = 0; ii < 12; ii++) t12[ii] = ech12[ii];
                if (!ins_ech(t12, vv)) continue;
                for (int ii = 0; ii < 4;  ii++) echn[ii]  = tn[ii];
                for (int ii = 0; ii < 12; ii++) ech12[ii] = t12[ii];
                sel[nsel++] = vv;
            }
        } else {
            // dense sweeps: b0..b2 with GF(2)-independent swizzled LOW-3-BITS
            // -> every 8-lane phase of LDS.128/STS.128 hits distinct 16B bank
            // groups (conflict-free u128 state access). Implies nibble rank 3.
            int ech3[3] = {};
            for (int c = 1; c < 512 && nsel < 3; c++) {
                int vv = 0;
                for (int bb = 0; bb < 9; bb++) if ((c >> bb) & 1) vv ^= bas[bb];
                int t3[3] = {ech3[0], ech3[1], ech3[2]};
                if (!ins_ech(t3, csw(vv) & 7)) continue;
                int t12[12] = {};
                for (int ii = 0; ii < 12; ii++) t12[ii] = ech12[ii];
                if (!ins_ech(t12, vv)) continue;
                for (int ii = 0; ii < 3;  ii++) ech3[ii]  = t3[ii];
                for (int ii = 0; ii < 12; ii++) ech12[ii] = t12[ii];
                sel[nsel++] = vv;
            }
            // b3: extend swizzled nibble rank to 4 (16-lane coverage)
            int echn[4] = {};
            for (int s0 = 0; s0 < nsel; s0++) ins_ech(echn, csw(sel[s0]) & 15);
            for (int c = 1; c < 512 && nsel < 4; c++) {
                int vv = 0;
                for (int bb = 0; bb < 9; bb++) if ((c >> bb) & 1) vv ^= bas[bb];
                int tn[4] = {echn[0], echn[1], echn[2], echn[3]};
                if (!ins_ech(tn, csw(vv) & 15)) continue;
                int t12[12] = {};
                for (int ii = 0; ii < 12; ii++) t12[ii] = ech12[ii];
                if (!ins_ech(t12, vv)) continue;
                for (int ii = 0; ii < 4;  ii++) echn[ii]  = tn[ii];
                for (int ii = 0; ii < 12; ii++) ech12[ii] = t12[ii];
                sel[nsel++] = vv;
            }
        }
        // complete to rank 9
        for (int bb = 0; bb < 9 && nsel < 9; bb++)
            if (ins_ech(ech12, bas[bb])) sel[nsel++] = bas[bb];
        t.sp[idx][0] = csw(rawv[idx][0]);
        t.sp[idx][1] = csw(rawv[idx][1]);
        t.sp[idx][2] = csw(rawv[idx][2]);
        for (int jj = 0; jj < 9; jj++) t.sp[idx][3 + jj] = csw(sel[jj]);
    }
    for (int c = 0; c < NC; c++) {
        const int d = Mp[NL][NQ - 1 - c];
        t.dz[c] = (d ^ (d << 4) ^ (d << 8)) & 0xFFF;
    }
    return t;
}

__constant__ Tab c_tab = make_tab();

// ---------------- packed f32x2 helpers ----------------
__device__ __forceinline__ u64 fma2(u64 a, u64 b, u64 c) {
    u64 d; asm("fma.rn.f32x2 %0, %1, %2, %3;" : "=l"(d) : "l"(a), "l"(b), "l"(c));
    return d;
}
__device__ __forceinline__ u64 mul2(u64 a, u64 b) {
    u64 d; asm("mul.rn.f32x2 %0, %1, %2;" : "=l"(d) : "l"(a), "l"(b));
    return d;
}
__device__ __forceinline__ u64 add2(u64 a, u64 b) {
    u64 d; asm("add.rn.f32x2 %0, %1, %2;" : "=l"(d) : "l"(a), "l"(b));
    return d;
}
__device__ __forceinline__ u64 pack2(float lo, float hi) {
    u64 d; asm("mov.b64 %0, {%1, %2};" : "=l"(d) : "f"(lo), "f"(hi));
    return d;
}
__device__ __forceinline__ float lo32(u64 v) { return __uint_as_float((unsigned)v); }
__device__ __forceinline__ float hi32(u64 v) { return __uint_as_float((unsigned)(v >> 32)); }
__device__ __forceinline__ u64 shfl_down64(u64 v, int o) {
    unsigned lo = (unsigned)v, hi = (unsigned)(v >> 32);
    lo = __shfl_down_sync(0xffffffffu, lo, o);
    hi = __shfl_down_sync(0xffffffffu, hi, o);
    return ((u64)hi << 32) | lo;
}

// lane-parallel SU(2) gate: lane0 = sample0's gate, lane1 = sample1's.
struct PGL { u64 ar, ai, nai, br, nbr, bi, nbi; };

__device__ __forceinline__ void pgl(const PGL& g, u64& are, u64& aim,
                                    u64& bre, u64& bim) {
    u64 nre = mul2(g.ar, are);
    nre = fma2(g.nai, aim, nre);
    nre = fma2(g.br,  bre, nre);
    nre = fma2(g.nbi, bim, nre);
    u64 nim = mul2(g.ar, aim);
    nim = fma2(g.ai,  are, nim);
    nim = fma2(g.br,  bim, nim);
    nim = fma2(g.bi,  bre, nim);
    u64 ore = mul2(g.nbr, are);
    ore = fma2(g.nbi, aim, ore);
    ore = fma2(g.ar,  bre, ore);
    ore = fma2(g.ai,  bim, ore);
    u64 oim = mul2(g.nbr, aim);
    oim = fma2(g.bi,  are, oim);
    oim = fma2(g.ar,  bim, oim);
    oim = fma2(g.nai, bre, oim);
    are = nre; aim = nim; bre = ore; bim = oim;
}
// gate rows padded to 64B; load as 4x LDS.128 (broadcast)
__device__ __forceinline__ PGL ldpg(const u64* p) {
    const ulonglong2* p2 = reinterpret_cast<const ulonglong2*>(p);
    const ulonglong2 a = p2[0], b = p2[1], c = p2[2], d = p2[3];
    PGL g = {a.x, a.y, b.x, b.y, c.x, c.y, d.x};
    return g;
}

extern __shared__ ulonglong2 sdyn2[];  // st[DIM] u128 = (re u64, im u64), 64 KB

__global__ __launch_bounds__(TPB, 2) void vqc_kernel(const float* __restrict__ x,
                                                     const float* __restrict__ w,
                                                     const float* __restrict__ bias,
                                                     const float* __restrict__ gamma,
                                                     const float* __restrict__ beta,
                                                     float* __restrict__ out) {
    ulonglong2* st = sdyn2;
    __shared__ __align__(16) u64 s_ga[NL * NQ][8];  // gate consts, 64B rows
    __shared__ float s_ez[2][NC];
    __shared__ unsigned s_last;

    const int b0 = blockIdx.x * 2;       // samples b0, b0+1 (lanes 0, 1)
    const int tid = threadIdx.x;

    if (tid < 2 * NC) (&s_ez[0][0])[tid] = 0.0f;

    // ---- fused gates U = Rot(w) @ RY(x) for both samples, lane-packed ----
    if (tid < NL * NQ) {
        const int l = tid / NQ, q = tid % NQ;
        const float phi = w[(l * NQ + q) * 3 + 0];
        const float th  = w[(l * NQ + q) * 3 + 1];
        const float om  = w[(l * NQ + q) * 3 + 2];
        float stt, ct; sincosf(0.5f * th, &stt, &ct);
        const float a1 = -0.5f * (phi + om);
        const float a2 =  0.5f * (phi - om);
        float s1, c1, s2, c2;
        sincosf(a1, &s1, &c1);
        sincosf(a2, &s2, &c2);
        const float R00r =  c1 * ct, R00i =  s1 * ct;
        const float R01r = -c2 * stt, R01i = -s2 * stt;
        float2 al[2], be[2];
#pragma unroll
        for (int s = 0; s < 2; s++) {
            const float xh = 0.5f * x[(b0 + s) * NQ + q];
            float sy, cy; sincosf(xh, &sy, &cy);
            al[s] = make_float2( R00r * cy + R01r * sy,  R00i * cy + R01i * sy);
            be[s] = make_float2(-R00r * sy + R01r * cy, -R00i * sy + R01i * cy);
        }
        s_ga[tid][0] = pack2( al[0].x,  al[1].x);
        s_ga[tid][1] = pack2( al[0].y,  al[1].y);
        s_ga[tid][2] = pack2(-al[0].y, -al[1].y);
        s_ga[tid][3] = pack2( be[0].x,  be[1].x);
        s_ga[tid][4] = pack2(-be[0].x, -be[1].x);
        s_ga[tid][5] = pack2( be[0].y,  be[1].y);
        s_ga[tid][6] = pack2(-be[0].y, -be[1].y);
        s_ga[tid][7] = 0ull;
    }
    __syncthreads();

    // ---- sweep 0, fused with state init: thread 0 computes its octet from
    // the register-known |0...0> (no loads); all other threads' octets are
    // provably zero, so they just zero-fill (covers all 4096 slots). ----
    {
        const int sv1 = c_tab.sp[0][0];
        const int sv2 = c_tab.sp[0][1];
        const int sv3 = c_tab.sp[0][2];
        int base = 0;
#pragma unroll
        for (int jj = 0; jj < 9; jj++)
            base ^= ((tid >> jj) & 1) ? c_tab.sp[0][3 + jj] : 0;
        int j[8];
#pragma unroll
        for (int m = 0; m < 8; m++)
            j[m] = base ^ ((m & 1) ? sv1 : 0) ^ ((m & 2) ? sv2 : 0)
                        ^ ((m & 4) ? sv3 : 0);
        if (tid == 0) {
            u64 re[8], im[8];
#pragma unroll
            for (int m = 0; m < 8; m++) { re[m] = 0ull; im[m] = 0ull; }
            re[0] = pack2(1.0f, 1.0f);                       // slot 0 (sw(0)==0)
            {
                const PGL G = ldpg(s_ga[2]);                 // qubit 2
                pgl(G, re[0], im[0], re[4], im[4]);
                pgl(G, re[1], im[1], re[5], im[5]);
                pgl(G, re[2], im[2], re[6], im[6]);
                pgl(G, re[3], im[3], re[7], im[7]);
            }
            {
                const PGL G = ldpg(s_ga[1]);                 // qubit 1
                pgl(G, re[0], im[0], re[2], im[2]);
                pgl(G, re[1], im[1], re[3], im[3]);
                pgl(G, re[4], im[4], re[6], im[6]);
                pgl(G, re[5], im[5], re[7], im[7]);
            }
            {
                const PGL G = ldpg(s_ga[0]);                 // qubit 0
                pgl(G, re[0], im[0], re[1], im[1]);
                pgl(G, re[2], im[2], re[3], im[3]);
                pgl(G, re[4], im[4], re[5], im[5]);
                pgl(G, re[6], im[6], re[7], im[7]);
            }
#pragma unroll
            for (int m = 0; m < 8; m++) st[j[m]] = make_ulonglong2(re[m], im[m]);
        } else {
            const ulonglong2 z = make_ulonglong2(0ull, 0ull);
#pragma unroll
            for (int m = 0; m < 8; m++) st[j[m]] = z;
        }
    }
    __syncthreads();

    // ---- sweeps 1..14 (CNOT rings folded into masks) ----
    for (int swp = 1; swp < NSWEEP - 1; swp++) {
        const int l = swp >> 2, g = swp & 3;
        // layer-0 sparsity: active set is exactly tid < 8^swp (basis-ordered)
        const bool act = (swp >= 3) ? true : (tid < (1 << (3 * swp)));
        if (act) {
            const int sv1 = c_tab.sp[swp][0];
            const int sv2 = c_tab.sp[swp][1];
            const int sv3 = c_tab.sp[swp][2];
            int base = 0;
#pragma unroll
            for (int jj = 0; jj < 9; jj++)
                base ^= ((tid >> jj) & 1) ? c_tab.sp[swp][3 + jj] : 0;
            int j[8];
#pragma unroll
            for (int m = 0; m < 8; m++)
                j[m] = base ^ ((m & 1) ? sv1 : 0) ^ ((m & 2) ? sv2 : 0)
                            ^ ((m & 4) ? sv3 : 0);
            u64 re[8], im[8];
#pragma unroll
            for (int m = 0; m < 8; m++) {
                const ulonglong2 v = st[j[m]];
                re[m] = v.x; im[m] = v.y;
            }
            {   // gate on qubit 3g+2 (mask v3): pairs (m, m^4) -- 4 independent
                const PGL G = ldpg(s_ga[l * NQ + 3 * g + 2]);
                pgl(G, re[0], im[0], re[4], im[4]);
                pgl(G, re[1], im[1], re[5], im[5]);
                pgl(G, re[2], im[2], re[6], im[6]);
                pgl(G, re[3], im[3], re[7], im[7]);
            }
            {   // gate on qubit 3g+1 (mask v2): pairs (m, m^2)
                const PGL G = ldpg(s_ga[l * NQ + 3 * g + 1]);
                pgl(G, re[0], im[0], re[2], im[2]);
                pgl(G, re[1], im[1], re[3], im[3]);
                pgl(G, re[4], im[4], re[6], im[6]);
                pgl(G, re[5], im[5], re[7], im[7]);
            }
            {   // gate on qubit 3g (mask v1): pairs (m, m^1)
                const PGL G = ldpg(s_ga[l * NQ + 3 * g + 0]);
                pgl(G, re[0], im[0], re[1], im[1]);
                pgl(G, re[2], im[2], re[3], im[3]);
                pgl(G, re[4], im[4], re[5], im[5]);
                pgl(G, re[6], im[6], re[7], im[7]);
            }
#pragma unroll
            for (int m = 0; m < 8; m++) st[j[m]] = make_ulonglong2(re[m], im[m]);
        }
        __syncthreads();
    }

    // ---- peeled final sweep (15) with measurement fused from registers ----
    // ez declared HERE so it is not live during the sweep loop (no spills).
    u64 ez[NC];
#pragma unroll
    for (int c = 0; c < NC; c++) ez[c] = 0ull;
    {
        const int swp = NSWEEP - 1;
        const int l = swp >> 2, g = swp & 3;
        const int sv1 = c_tab.sp[swp][0];
        const int sv2 = c_tab.sp[swp][1];
        const int sv3 = c_tab.sp[swp][2];
        int base = 0;
#pragma unroll
        for (int jj = 0; jj < 9; jj++)
            base ^= ((tid >> jj) & 1) ? c_tab.sp[swp][3 + jj] : 0;
        int j[8];
#pragma unroll
        for (int m = 0; m < 8; m++)
            j[m] = base ^ ((m & 1) ? sv1 : 0) ^ ((m & 2) ? sv2 : 0)
                        ^ ((m & 4) ? sv3 : 0);
        u64 re[8], im[8];
#pragma unroll
        for (int m = 0; m < 8; m++) {
            const ulonglong2 v = st[j[m]];
            re[m] = v.x; im[m] = v.y;
        }
        {
            const PGL G = ldpg(s_ga[l * NQ + 3 * g + 2]);
            pgl(G, re[0], im[0], re[4], im[4]);
            pgl(G, re[1], im[1], re[5], im[5]);
            pgl(G, re[2], im[2], re[6], im[6]);
            pgl(G, re[3], im[3], re[7], im[7]);
        }
        {
            const PGL G = ldpg(s_ga[l * NQ + 3 * g + 1]);
            pgl(G, re[0], im[0], re[2], im[2]);
            pgl(G, re[1], im[1], re[3], im[3]);
            pgl(G, re[4], im[4], re[6], im[6]);
            pgl(G, re[5], im[5], re[7], im[7]);
        }
        {
            const PGL G = ldpg(s_ga[l * NQ + 3 * g + 0]);
            pgl(G, re[0], im[0], re[1], im[1]);
            pgl(G, re[2], im[2], re[3], im[3]);
            pgl(G, re[4], im[4], re[5], im[5]);
            pgl(G, re[6], im[6], re[7], im[7]);
        }
        // final state is dead after measurement: accumulate <Z_c> directly
        // from registers (no store, no barrier, no read-back pass).
        const u64 ONEP = 0x3F8000003F800000ull, ONEN = 0xBF800000BF800000ull;
#pragma unroll
        for (int m = 0; m < 8; m++) {
            const u64 p = fma2(re[m], re[m], mul2(im[m], im[m]));
#pragma unroll
            for (int c = 0; c < NC; c++) {
                const u64 sgn = (__popc(j[m] & c_tab.dz[c]) & 1) ? ONEN : ONEP;
                ez[c] = fma2(p, sgn, ez[c]);
            }
        }
    }

    // ---- reduce <Z_c> (warp shuffle + shared atomics) ----
#pragma unroll
    for (int c = 0; c < NC; c++) {
        u64 v = ez[c];
        for (int o = 16; o > 0; o >>= 1) v = add2(v, shfl_down64(v, o));
        if ((tid & 31) == 0) {
            atomicAdd(&s_ez[0][c], lo32(v));
            atomicAdd(&s_ez[1][c], hi32(v));
        }
    }
    __syncthreads();

    // ---- softmax(expz + bias): thread 0 -> sample b0, thread 1 -> b0+1 ----
    if (tid < 2) {
        float z[NC];
        float m = -1e30f;
#pragma unroll
        for (int c = 0; c < NC; c++) {
            z[c] = s_ez[tid][c] + bias[c];
            m = fmaxf(m, z[c]);
        }
        float sum = 0.0f;
#pragma unroll
        for (int c = 0; c < NC; c++) {
            z[c] = expf(z[c] - m);
            sum += z[c];
        }
        const float inv = 1.0f / sum;
#pragma unroll
        for (int c = 0; c < NC; c++) g_probs[(b0 + tid) * NC + c] = z[c] * inv;
    }
    __syncthreads();
    if (tid == 0) {
        __threadfence();
        s_last = atomicAdd(&g_cnt, 1u);
    }
    __syncthreads();

    // ---- BN epilogue: performed entirely by the last-arriving block ----
    if (s_last == NBLK - 1u) {
        if (tid == 0) g_cnt = 0;          // reset for next (graph-replayed) call
        __threadfence();                  // make all blocks' g_probs reads fresh

        __shared__ float smu[NC], srs[NC];
        const int wid = tid >> 5, lid = tid & 31;
        if (wid < NC) {
            const int c = wid;
            float s = 0.0f, q = 0.0f;
            for (int t2 = lid; t2 < BATCH; t2 += 32) {
                const float p = g_probs[t2 * NC + c];
                s += p; q += p * p;
            }
            for (int o = 16; o > 0; o >>= 1) {
                s += __shfl_down_sync(0xffffffffu, s, o);
                q += __shfl_down_sync(0xffffffffu, q, o);
            }
            if (lid == 0) {
                const float mu = s / (float)BATCH;
                smu[c] = mu;
                srs[c] = rsqrtf(q / (float)BATCH - mu * mu + BN_EPS);
            }
        }
        __syncthreads();
        for (int i = tid; i < BATCH * NC; i += TPB) {
            const int c = i % NC;
            out[i] = (g_probs[i] - smu[c]) * srs[c] * gamma[c] + beta[c];
        }
    }
}

extern "C" void kernel_launch(void* const* d_in, const int* in_sizes, int n_in,
                              void* d_out, int out_size) {
    const float* x      = (const float*)d_in[0];  // (512, 12)
    const float* wts    = (const float*)d_in[1];  // (4, 12, 3)
    const float* bias   = (const float*)d_in[2];  // (10,)
    const float* gamma  = (const float*)d_in[3];  // (10,)
    const float* beta   = (const float*)d_in[4];  // (10,)
    float* out = (float*)d_out;                   // (512, 10)

    const int smem_bytes = DIM * (int)sizeof(ulonglong2);   // 64 KB dynamic
    cudaFuncSetAttribute(vqc_kernel,
                         cudaFuncAttributeMaxDynamicSharedMemorySize, smem_bytes);
    vqc_kernel<<<NBLK, TPB, smem_bytes>>>(x, wts, bias, gamma, beta, out);
}

// round 17
// speedup vs baseline: 1.0466x; 1.0466x over previous
#include <cuda_runtime.h>
#include <math.h>

#define NQ 12
#define DIM 4096
#define NL 4
#define NC 10
#define BATCH 512
#define TPB 512
#define NBLK (BATCH / 2)     // 256 blocks, 2 samples per block (f32x2 lanes)
#define BN_EPS 1e-5f
#define NSWEEP (NL * 4)      // 16 three-qubit sweeps

typedef unsigned long long u64;

// Scratch for softmax probs (B x NC) + completion counter. Allocation-free.
__device__ float g_probs[BATCH * NC];
__device__ unsigned g_cnt = 0;

// ---------------- compile-time GF(2) circuit tables ----------------
// All builders are __host__ __device__ constexpr so device code may evaluate
// them in constant-expression contexts (constexpr locals -> immediates).
__host__ __device__ constexpr int csw(int i) { return i ^ (i >> 4); }
__host__ __device__ constexpr int cctz(int v) { int n = 0; while (!(v & 1)) { v >>= 1; n++; } return n; }
__host__ __device__ constexpr int cmsb(int v) { int n = -1; while (v) { v >>= 1; n++; } return n; }

__host__ __device__ constexpr bool ins_ech(int* ech, int v) {
    while (v) {
        const int m = cmsb(v);
        if (!ech[m]) { ech[m] = v; return true; }
        v ^= ech[m];
    }
    return false;
}
__host__ __device__ constexpr int red_ech(const int* ech, int v) {
    while (v) {
        const int m = cmsb(v);
        if (!ech[m]) return v;
        v ^= ech[m];
    }
    return 0;
}

struct Tab {
    int sp[NSWEEP][12];   // per sweep: sw(v1), sw(v2), sw(v3), sw(bas[0..8])
    int dz[NC];           // swizzled parity masks for <Z_c> with C^4 folded in
};

__host__ __device__ constexpr Tab make_tab() {
    Tab t{};
    int M[NQ] = {}, Mi[NQ] = {};
    for (int r = 0; r < NQ; r++) { M[r] = 1 << r; Mi[r] = 1 << r; }
    for (int q = 0; q < NQ; q++) {             // CNOT(q, q+1), q ascending
        int pc = NQ - 1 - q, pt = NQ - 1 - ((q + 1) % NQ);
        M[pt] ^= M[pc];
    }
    for (int q = NQ - 1; q >= 0; q--) {        // inverse: reversed order
        int pc = NQ - 1 - q, pt = NQ - 1 - ((q + 1) % NQ);
        Mi[pt] ^= Mi[pc];
    }
    int Mp[NL + 1][NQ] = {}, Mip[NL][NQ] = {};
    int P[NQ] = {}, Pi_[NQ] = {};
    for (int r = 0; r < NQ; r++) { P[r] = 1 << r; Pi_[r] = 1 << r; }
    for (int l = 0; l <= NL; l++) {
        for (int r = 0; r < NQ; r++) Mp[l][r] = P[r];
        if (l < NL) for (int r = 0; r < NQ; r++) Mip[l][r] = Pi_[r];
        int Pn[NQ] = {}, Pin[NQ] = {};
        for (int r = 0; r < NQ; r++) {
            int acc = 0, acci = 0;
            for (int s = 0; s < NQ; s++) {
                if ((M[r]  >> s) & 1) acc  ^= P[s];
                if ((Mi[r] >> s) & 1) acci ^= Pi_[s];
            }
            Pn[r] = acc; Pin[r] = acci;
        }
        for (int r = 0; r < NQ; r++) { P[r] = Pn[r]; Pi_[r] = Pin[r]; }
    }
    // raw gate masks per sweep (columns of M^{-l})
    int rawv[NSWEEP][3] = {};
    for (int idx = 0; idx < NSWEEP; idx++) {
        const int l = idx / 4, g = idx % 4;
        for (int j = 0; j < 3; j++) {
            const int pb = NQ - 1 - (3 * g + j);
            for (int r = 0; r < NQ; r++)
                rawv[idx][j] |= ((Mip[l][r] >> pb) & 1) << r;
        }
    }
    for (int idx = 0; idx < NSWEEP; idx++) {
        const int l = idx / 4, g = idx % 4;
        int D[3] = {};
        for (int j = 0; j < 3; j++) D[j] = Mp[l][NQ - 1 - (3 * g + j)];
        // RREF of the 3 duals
        int pv[3] = {};
        for (int j = 0; j < 3; j++) {
            pv[j] = cctz(D[j]);
            for (int i = 0; i < 3; i++)
                if (i != j && ((D[i] >> pv[j]) & 1)) D[i] ^= D[j];
        }
        // null-space basis (9 vectors)
        int bas[9] = {}; int nb = 0;
        const int pmask = (1 << pv[0]) | (1 << pv[1]) | (1 << pv[2]);
        for (int j = 0; j < NQ; j++) {
            if ((pmask >> j) & 1) continue;
            bas[nb++] = (1 << j) ^ (((D[0] >> j) & 1) << pv[0])
                                 ^ (((D[1] >> j) & 1) << pv[1])
                                 ^ (((D[2] >> j) & 1) << pv[2]);
        }
        int sel[9] = {}; int nsel = 0;
        int ech12[12] = {};           // echelon of chosen vectors
        int echn[4] = {};             // nibble echelon (swizzled low 4 bits)
        // Stage 1 (layer-0 sweeps 1,2 sparsity): support-subspace vectors on
        // low tid bits so active set == {tid < 8^swp}.
        if (idx >= 1 && idx < 3) {
            int Wech[12] = {};        // span of masks of sweeps 0..idx
            for (int s2 = 0; s2 <= idx; s2++)
                for (int j = 0; j < 3; j++) ins_ech(Wech, rawv[s2][j]);
            for (int c = 1; c < 512 && nsel < 3 * idx; c++) {
                int vv = 0;
                for (int bb = 0; bb < 9; bb++) if ((c >> bb) & 1) vv ^= bas[bb];
                if (red_ech(Wech, vv)) continue;              // not in support
                int t12[12] = {};
                for (int ii = 0; ii < 12; ii++) t12[ii] = ech12[ii];
                if (!ins_ech(t12, vv)) continue;              // dependent
                for (int ii = 0; ii < 12; ii++) ech12[ii] = t12[ii];
                ins_ech(echn, csw(vv) & 15);                  // seed nibble ech
                sel[nsel++] = vv;
            }
        }
        // Stage 2: bank-aware picks until lane bits 0..3 have independent
        // swizzled low nibbles (conflict-free LDS.64/STS.64 16-lane phases).
        int bankgoal = nsel + 4; if (bankgoal > 9) bankgoal = 9;
        for (int c = 1; c < 512 && nsel < bankgoal; c++) {
            int vv = 0;
            for (int bb = 0; bb < 9; bb++) if ((c >> bb) & 1) vv ^= bas[bb];
            int tn[4] = {echn[0], echn[1], echn[2], echn[3]};
            if (!ins_ech(tn, csw(vv) & 15)) continue;
            int t12[12] = {};
            for (int ii = 0; ii < 12; ii++) t12[ii] = ech12[ii];
            if (!ins_ech(t12, vv)) continue;
            for (int ii = 0; ii < 4;  ii++) echn[ii]  = tn[ii];
            for (int ii = 0; ii < 12; ii++) ech12[ii] = t12[ii];
            sel[nsel++] = vv;
        }
        // Stage 3: complete to rank 9
        for (int bb = 0; bb < 9 && nsel < 9; bb++)
            if (ins_ech(ech12, bas[bb])) sel[nsel++] = bas[bb];
        t.sp[idx][0] = csw(rawv[idx][0]);
        t.sp[idx][1] = csw(rawv[idx][1]);
        t.sp[idx][2] = csw(rawv[idx][2]);
        for (int jj = 0; jj < 9; jj++) t.sp[idx][3 + jj] = csw(sel[jj]);
    }
    for (int c = 0; c < NC; c++) {
        const int d = Mp[NL][NQ - 1 - c];
        t.dz[c] = (d ^ (d << 4) ^ (d << 8)) & 0xFFF;
    }
    return t;
}

// ---------------- packed f32x2 helpers ----------------
__device__ __forceinline__ u64 fma2(u64 a, u64 b, u64 c) {
    u64 d; asm("fma.rn.f32x2 %0, %1, %2, %3;" : "=l"(d) : "l"(a), "l"(b), "l"(c));
    return d;
}
__device__ __forceinline__ u64 mul2(u64 a, u64 b) {
    u64 d; asm("mul.rn.f32x2 %0, %1, %2;" : "=l"(d) : "l"(a), "l"(b));
    return d;
}
__device__ __forceinline__ u64 add2(u64 a, u64 b) {
    u64 d; asm("add.rn.f32x2 %0, %1, %2;" : "=l"(d) : "l"(a), "l"(b));
    return d;
}
__device__ __forceinline__ u64 pack2(float lo, float hi) {
    u64 d; asm("mov.b64 %0, {%1, %2};" : "=l"(d) : "f"(lo), "f"(hi));
    return d;
}
__device__ __forceinline__ float lo32(u64 v) { return __uint_as_float((unsigned)v); }
__device__ __forceinline__ float hi32(u64 v) { return __uint_as_float((unsigned)(v >> 32)); }
__device__ __forceinline__ u64 shfl_down64(u64 v, int o) {
    unsigned lo = (unsigned)v, hi = (unsigned)(v >> 32);
    lo = __shfl_down_sync(0xffffffffu, lo, o);
    hi = __shfl_down_sync(0xffffffffu, hi, o);
    return ((u64)hi << 32) | lo;
}

// lane-parallel SU(2) gate: lane0 = sample0's gate, lane1 = sample1's.
struct PGL { u64 ar, ai, nai, br, nbr, bi, nbi; };

__device__ __forceinline__ void pgl(const PGL& g, u64& are, u64& aim,
                                    u64& bre, u64& bim) {
    u64 nre = mul2(g.ar, are);
    nre = fma2(g.nai, aim, nre);
    nre = fma2(g.br,  bre, nre);
    nre = fma2(g.nbi, bim, nre);
    u64 nim = mul2(g.ar, aim);
    nim = fma2(g.ai,  are, nim);
    nim = fma2(g.br,  bim, nim);
    nim = fma2(g.bi,  bre, nim);
    u64 ore = mul2(g.nbr, are);
    ore = fma2(g.nbi, aim, ore);
    ore = fma2(g.ar,  bre, ore);
    ore = fma2(g.ai,  bim, ore);
    u64 oim = mul2(g.nbr, aim);
    oim = fma2(g.bi,  are, oim);
    oim = fma2(g.ar,  bim, oim);
    oim = fma2(g.nai, bre, oim);
    are = nre; aim = nim; bre = ore; bim = oim;
}
__device__ __forceinline__ PGL ldpg(const u64* p) {
    PGL g = {p[0], p[1], p[2], p[3], p[4], p[5], p[6]};
    return g;
}

extern __shared__ u64 sdyn[];  // st_re[DIM] ++ st_im[DIM] = 64 KB

// one three-qubit sweep; all table entries extracted as constexpr scalars
// (device-local constant expressions -> instruction immediates, no LDC)
template<int SWP>
__device__ __forceinline__ void sweep(u64* __restrict__ st_re,
                                      u64* __restrict__ st_im,
                                      const u64 (*s_ga)[7], int tid) {
    // layer-0 sparsity: active set is exactly tid < 8^SWP (basis-ordered)
    if (SWP < 3 && tid >= (1 << (3 * SWP))) return;

    constexpr Tab t = make_tab();
    constexpr int l = SWP >> 2, g = SWP & 3;
    constexpr int sv1 = t.sp[SWP][0];
    constexpr int sv2 = t.sp[SWP][1];
    constexpr int sv3 = t.sp[SWP][2];
    constexpr int B0 = t.sp[SWP][3],  B1 = t.sp[SWP][4],  B2 = t.sp[SWP][5];
    constexpr int B3 = t.sp[SWP][6],  B4 = t.sp[SWP][7],  B5 = t.sp[SWP][8];
    constexpr int B6 = t.sp[SWP][9],  B7 = t.sp[SWP][10], B8 = t.sp[SWP][11];

    const int base = ((tid >> 0) & 1 ? B0 : 0) ^ ((tid >> 1) & 1 ? B1 : 0)
                   ^ ((tid >> 2) & 1 ? B2 : 0) ^ ((tid >> 3) & 1 ? B3 : 0)
                   ^ ((tid >> 4) & 1 ? B4 : 0) ^ ((tid >> 5) & 1 ? B5 : 0)
                   ^ ((tid >> 6) & 1 ? B6 : 0) ^ ((tid >> 7) & 1 ? B7 : 0)
                   ^ ((tid >> 8) & 1 ? B8 : 0);

    int j[8];
#pragma unroll
    for (int m = 0; m < 8; m++)
        j[m] = base ^ ((m & 1) ? sv1 : 0) ^ ((m & 2) ? sv2 : 0)
                    ^ ((m & 4) ? sv3 : 0);

    u64 re[8], im[8];
#pragma unroll
    for (int m = 0; m < 8; m++) { re[m] = st_re[j[m]]; im[m] = st_im[j[m]]; }

    {   // gate on qubit 3g+2 (mask v3): pairs (m, m^4) -- 4 independent
        const PGL G = ldpg(s_ga[l * NQ + 3 * g + 2]);
        pgl(G, re[0], im[0], re[4], im[4]);
        pgl(G, re[1], im[1], re[5], im[5]);
        pgl(G, re[2], im[2], re[6], im[6]);
        pgl(G, re[3], im[3], re[7], im[7]);
    }
    {   // gate on qubit 3g+1 (mask v2): pairs (m, m^2)
        const PGL G = ldpg(s_ga[l * NQ + 3 * g + 1]);
        pgl(G, re[0], im[0], re[2], im[2]);
        pgl(G, re[1], im[1], re[3], im[3]);
        pgl(G, re[4], im[4], re[6], im[6]);
        pgl(G, re[5], im[5], re[7], im[7]);
    }
    {   // gate on qubit 3g (mask v1): pairs (m, m^1)
        const PGL G = ldpg(s_ga[l * NQ + 3 * g + 0]);
        pgl(G, re[0], im[0], re[1], im[1]);
        pgl(G, re[2], im[2], re[3], im[3]);
        pgl(G, re[4], im[4], re[5], im[5]);
        pgl(G, re[6], im[6], re[7], im[7]);
    }
#pragma unroll
    for (int m = 0; m < 8; m++) { st_re[j[m]] = re[m]; st_im[j[m]] = im[m]; }
}

__global__ __launch_bounds__(TPB, 2) void vqc_kernel(const float* __restrict__ x,
                                                     const float* __restrict__ w,
                                                     const float* __restrict__ bias,
                                                     const float* __restrict__ gamma,
                                                     const float* __restrict__ beta,
                                                     float* __restrict__ out) {
    u64* st_re = sdyn;
    u64* st_im = sdyn + DIM;
    __shared__ u64 s_ga[NL * NQ][7];     // packed per-lane gate constants
    __shared__ float s_ez[2][NC];
    __shared__ unsigned s_last;

    const int b0 = blockIdx.x * 2;       // samples b0, b0+1 (lanes 0, 1)
    const int tid = threadIdx.x;

    // ---- init state (both lanes |0...0>) ----
    for (int i = tid; i < DIM; i += TPB) {
        st_re[i] = (i == 0) ? pack2(1.0f, 1.0f) : 0ull;   // sw(0)==0
        st_im[i] = 0ull;
    }
    if (tid < 2 * NC) (&s_ez[0][0])[tid] = 0.0f;

    // ---- fused gates U = Rot(w) @ RY(x) for both samples, lane-packed ----
    if (tid < NL * NQ) {
        const int l = tid / NQ, q = tid % NQ;
        const float phi = w[(l * NQ + q) * 3 + 0];
        const float th  = w[(l * NQ + q) * 3 + 1];
        const float om  = w[(l * NQ + q) * 3 + 2];
        float stt, ct; sincosf(0.5f * th, &stt, &ct);
        const float a1 = -0.5f * (phi + om);
        const float a2 =  0.5f * (phi - om);
        float s1, c1, s2, c2;
        sincosf(a1, &s1, &c1);
        sincosf(a2, &s2, &c2);
        const float R00r =  c1 * ct, R00i =  s1 * ct;
        const float R01r = -c2 * stt, R01i = -s2 * stt;
        float2 al[2], be[2];
#pragma unroll
        for (int s = 0; s < 2; s++) {
            const float xh = 0.5f * x[(b0 + s) * NQ + q];
            float sy, cy; sincosf(xh, &sy, &cy);
            al[s] = make_float2( R00r * cy + R01r * sy,  R00i * cy + R01i * sy);
            be[s] = make_float2(-R00r * sy + R01r * cy, -R00i * sy + R01i * cy);
        }
        s_ga[tid][0] = pack2( al[0].x,  al[1].x);
        s_ga[tid][1] = pack2( al[0].y,  al[1].y);
        s_ga[tid][2] = pack2(-al[0].y, -al[1].y);
        s_ga[tid][3] = pack2( be[0].x,  be[1].x);
        s_ga[tid][4] = pack2(-be[0].x, -be[1].x);
        s_ga[tid][5] = pack2( be[0].y,  be[1].y);
        s_ga[tid][6] = pack2(-be[0].y, -be[1].y);
    }
    __syncthreads();

    // ---- sweeps 0..14, fully instantiated (immediates, no LDC) ----
    sweep<0>(st_re, st_im, s_ga, tid);  __syncthreads();
    sweep<1>(st_re, st_im, s_ga, tid);  __syncthreads();
    sweep<2>(st_re, st_im, s_ga, tid);  __syncthreads();
    sweep<3>(st_re, st_im, s_ga, tid);  __syncthreads();
    sweep<4>(st_re, st_im, s_ga, tid);  __syncthreads();
    sweep<5>(st_re, st_im, s_ga, tid);  __syncthreads();
    sweep<6>(st_re, st_im, s_ga, tid);  __syncthreads();
    sweep<7>(st_re, st_im, s_ga, tid);  __syncthreads();
    sweep<8>(st_re, st_im, s_ga, tid);  __syncthreads();
    sweep<9>(st_re, st_im, s_ga, tid);  __syncthreads();
    sweep<10>(st_re, st_im, s_ga, tid); __syncthreads();
    sweep<11>(st_re, st_im, s_ga, tid); __syncthreads();
    sweep<12>(st_re, st_im, s_ga, tid); __syncthreads();
    sweep<13>(st_re, st_im, s_ga, tid); __syncthreads();
    sweep<14>(st_re, st_im, s_ga, tid); __syncthreads();

    // ---- peeled final sweep (15) with measurement fused from registers ----
    // ez declared HERE so it is not live during the sweeps (no spills).
    u64 ez[NC];
#pragma unroll
    for (int c = 0; c < NC; c++) ez[c] = 0ull;
    {
        constexpr Tab t = make_tab();
        constexpr int SWP = NSWEEP - 1;
        constexpr int l = SWP >> 2, g = SWP & 3;
        constexpr int sv1 = t.sp[SWP][0];
        constexpr int sv2 = t.sp[SWP][1];
        constexpr int sv3 = t.sp[SWP][2];
        constexpr int B0 = t.sp[SWP][3],  B1 = t.sp[SWP][4],  B2 = t.sp[SWP][5];
        constexpr int B3 = t.sp[SWP][6],  B4 = t.sp[SWP][7],  B5 = t.sp[SWP][8];
        constexpr int B6 = t.sp[SWP][9],  B7 = t.sp[SWP][10], B8 = t.sp[SWP][11];
        const int base = ((tid >> 0) & 1 ? B0 : 0) ^ ((tid >> 1) & 1 ? B1 : 0)
                       ^ ((tid >> 2) & 1 ? B2 : 0) ^ ((tid >> 3) & 1 ? B3 : 0)
                       ^ ((tid >> 4) & 1 ? B4 : 0) ^ ((tid >> 5) & 1 ? B5 : 0)
                       ^ ((tid >> 6) & 1 ? B6 : 0) ^ ((tid >> 7) & 1 ? B7 : 0)
                       ^ ((tid >> 8) & 1 ? B8 : 0);
        int j[8];
#pragma unroll
        for (int m = 0; m < 8; m++)
            j[m] = base ^ ((m & 1) ? sv1 : 0) ^ ((m & 2) ? sv2 : 0)
                        ^ ((m & 4) ? sv3 : 0);
        u64 re[8], im[8];
#pragma unroll
        for (int m = 0; m < 8; m++) { re[m] = st_re[j[m]]; im[m] = st_im[j[m]]; }
        {
            const PGL G = ldpg(s_ga[l * NQ + 3 * g + 2]);
            pgl(G, re[0], im[0], re[4], im[4]);
            pgl(G, re[1], im[1], re[5], im[5]);
            pgl(G, re[2], im[2], re[6], im[6]);
            pgl(G, re[3], im[3], re[7], im[7]);
        }
        {
            const PGL G = ldpg(s_ga[l * NQ + 3 * g + 1]);
            pgl(G, re[0], im[0], re[2], im[2]);
            pgl(G, re[1], im[1], re[3], im[3]);
            pgl(G, re[4], im[4], re[6], im[6]);
            pgl(G, re[5], im[5], re[7], im[7]);
        }
        {
            const PGL G = ldpg(s_ga[l * NQ + 3 * g + 0]);
            pgl(G, re[0], im[0], re[1], im[1]);
            pgl(G, re[2], im[2], re[3], im[3]);
            pgl(G, re[4], im[4], re[5], im[5]);
            pgl(G, re[6], im[6], re[7], im[7]);
        }
        // final state is dead after measurement: accumulate <Z_c> directly
        // from registers (no store, no barrier, no read-back pass).
        constexpr int DZ[NC] = {t.dz[0], t.dz[1], t.dz[2], t.dz[3], t.dz[4],
                                t.dz[5], t.dz[6], t.dz[7], t.dz[8], t.dz[9]};
        const u64 ONEP = 0x3F8000003F800000ull, ONEN = 0xBF800000BF800000ull;
#pragma unroll
        for (int m = 0; m < 8; m++) {
            const u64 p = fma2(re[m], re[m], mul2(im[m], im[m]));
#pragma unroll
            for (int c = 0; c < NC; c++) {
                const u64 sgn = (__popc(j[m] & DZ[c]) & 1) ? ONEN : ONEP;
                ez[c] = fma2(p, sgn, ez[c]);
            }
        }
    }

    // ---- reduce <Z_c> (warp shuffle + shared atomics) ----
#pragma unroll
    for (int c = 0; c < NC; c++) {
        u64 v = ez[c];
        for (int o = 16; o > 0; o >>= 1) v = add2(v, shfl_down64(v, o));
        if ((tid & 31) == 0) {
            atomicAdd(&s_ez[0][c], lo32(v));
            atomicAdd(&s_ez[1][c], hi32(v));
        }
    }
    __syncthreads();

    // ---- softmax(expz + bias): thread 0 -> sample b0, thread 1 -> b0+1 ----
    if (tid < 2) {
        float z[NC];
        float m = -1e30f;
#pragma unroll
        for (int c = 0; c < NC; c++) {
            z[c] = s_ez[tid][c] + bias[c];
            m = fmaxf(m, z[c]);
        }
        float sum = 0.0f;
#pragma unroll
        for (int c = 0; c < NC; c++) {
            z[c] = expf(z[c] - m);
            sum += z[c];
        }
        const float inv = 1.0f / sum;
#pragma unroll
        for (int c = 0; c < NC; c++) g_probs[(b0 + tid) * NC + c] = z[c] * inv;
    }
    __syncthreads();
    if (tid == 0) {
        __threadfence();
        s_last = atomicAdd(&g_cnt, 1u);
    }
    __syncthreads();

    // ---- BN epilogue: performed entirely by the last-arriving block ----
    if (s_last == NBLK - 1u) {
        if (tid == 0) g_cnt = 0;          // reset for next (graph-replayed) call
        __threadfence();                  // make all blocks' g_probs reads fresh

        __shared__ float smu[NC], srs[NC];
        const int wid = tid >> 5, lid = tid & 31;
        if (wid < NC) {
            const int c = wid;
            float s = 0.0f, q = 0.0f;
            for (int t2 = lid; t2 < BATCH; t2 += 32) {
                const float p = g_probs[t2 * NC + c];
                s += p; q += p * p;
            }
            for (int o = 16; o > 0; o >>= 1) {
                s += __shfl_down_sync(0xffffffffu, s, o);
                q += __shfl_down_sync(0xffffffffu, q, o);
            }
            if (lid == 0) {
                const float mu = s / (float)BATCH;
                smu[c] = mu;
                srs[c] = rsqrtf(q / (float)BATCH - mu * mu + BN_EPS);
            }
        }
        __syncthreads();
        for (int i = tid; i < BATCH * NC; i += TPB) {
            const int c = i % NC;
            out[i] = (g_probs[i] - smu[c]) * srs[c] * gamma[c] + beta[c];
        }
    }
}

extern "C" void kernel_launch(void* const* d_in, const int* in_sizes, int n_in,
                              void* d_out, int out_size) {
    const float* x      = (const float*)d_in[0];  // (512, 12)
    const float* wts    = (const float*)d_in[1];  // (4, 12, 3)
    const float* bias   = (const float*)d_in[2];  // (10,)
    const float* gamma  = (const float*)d_in[3];  // (10,)
    const float* beta   = (const float*)d_in[4];  // (10,)
    float* out = (float*)d_out;                   // (512, 10)

    const int smem_bytes = 2 * DIM * (int)sizeof(u64);   // 64 KB dynamic
    cudaFuncSetAttribute(vqc_kernel,
                         cudaFuncAttributeMaxDynamicSharedMemorySize, smem_bytes);
    vqc_kernel<<<NBLK, TPB, smem_bytes>>>(x, wts, bias, gamma, beta, out);
}